// round 15
// baseline (speedup 1.0000x reference)
#include <cuda_runtime.h>
#include <cuda_bf16.h>
#include <cstdint>
#include <cstddef>

#define DEVFN __device__ __forceinline__

constexpr int B = 16, N = 96, HID = 128, EF = 32, L = 4;
constexpr int BN = B * N;
constexpr float CUTOFF = 10.0f, RBF_GAMMA = 10.0f;
constexpr float PI_F = 3.14159265358979323846f;

// ---------------- scratch (device globals) ----------------
__device__ uint32_t g_maskh[(size_t)BN * N * (HID / 2)];  // bf16x2 mask
__device__ float g_s0[BN * HID];
__device__ float g_s[BN * HID];
__device__ float g_s1[BN * HID];
__device__ float g_s1b[BN * HID];
__device__ float g_v[BN * 3 * HID];
__device__ float g_qv[BN * 3 * HID];
__device__ float g_kv[BN * 3 * HID];
__device__ float g_ea[BN * N];
__device__ float g_ev[BN * N * 3];
__device__ uint32_t g_W1p[128 * 256];  // Wd1 packed bf16x2 (k-pairs)
__device__ uint32_t g_W2p[128 * 128];  // Wd2 packed bf16x2

DEVFN float silu_f(float x) { return x / (1.0f + __expf(-x)); }

DEVFN void fma4(float4& a, float x, const float4 w) {
    a.x = fmaf(x, w.x, a.x);
    a.y = fmaf(x, w.y, a.y);
    a.z = fmaf(x, w.z, a.z);
    a.w = fmaf(x, w.w, a.w);
}

DEVFN uint32_t packbf(float lo, float hi) {
    uint32_t r;
    asm("cvt.rn.bf16x2.f32 %0, %1, %2;" : "=r"(r) : "f"(hi), "f"(lo));
    return r;
}
DEVFN float2 unpackbf(uint32_t u) {
    __nv_bfloat162 b = *reinterpret_cast<__nv_bfloat162*>(&u);
    return __bfloat1622float2(b);
}

DEVFN uint32_t f2tf(float x) {
    uint32_t r;
    asm("cvt.rna.tf32.f32 %0, %1;" : "=r"(r) : "f"(x));
    return r;
}

DEVFN void mma16(float c[4], uint32_t a0, uint32_t a1, uint32_t a2, uint32_t a3,
                 uint32_t b0, uint32_t b1) {
    asm volatile(
        "mma.sync.aligned.m16n8k16.row.col.f32.bf16.bf16.f32 "
        "{%0,%1,%2,%3},{%4,%5,%6,%7},{%8,%9},{%0,%1,%2,%3};\n"
        : "+f"(c[0]), "+f"(c[1]), "+f"(c[2]), "+f"(c[3])
        : "r"(a0), "r"(a1), "r"(a2), "r"(a3), "r"(b0), "r"(b1));
}

DEVFN void mma8(float c[4], uint32_t a0, uint32_t a1, uint32_t a2, uint32_t a3,
                uint32_t b0, uint32_t b1) {
    asm volatile(
        "mma.sync.aligned.m16n8k8.row.col.f32.tf32.tf32.f32 "
        "{%0,%1,%2,%3},{%4,%5,%6,%7},{%8,%9},{%0,%1,%2,%3};\n"
        : "+f"(c[0]), "+f"(c[1]), "+f"(c[2]), "+f"(c[3])
        : "r"(a0), "r"(a1), "r"(a2), "r"(a3), "r"(b0), "r"(b1));
}

DEVFN float blksum128(float v, float* red) {
#pragma unroll
    for (int o = 16; o; o >>= 1) v += __shfl_xor_sync(0xffffffffu, v, o);
    if ((threadIdx.x & 31) == 0) red[threadIdx.x >> 5] = v;
    __syncthreads();
    float r = red[0] + red[1] + red[2] + red[3];
    __syncthreads();
    return r;
}

// ---------------- K-1: pack Wd1/Wd2 into bf16x2 k-pair layout ----------------
__global__ void k_prep(const float* __restrict__ Wd1, const float* __restrict__ Wd2) {
    int idx = blockIdx.x * 256 + threadIdx.x;
    if (idx < 128 * 256) {
        int kp = idx >> 8, n = idx & 255;
        g_W1p[idx] = packbf(Wd1[(2 * kp) * 256 + n], Wd1[(2 * kp + 1) * 256 + n]);
    } else {
        int r = idx - 128 * 256;
        if (r < 128 * 128) {
            int kp = r >> 7, n = r & 127;
            g_W2p[r] = packbf(Wd2[(2 * kp) * 128 + n], Wd2[(2 * kp + 1) * 128 + n]);
        }
    }
}

// ---------------- K0: s0 = LN(emb_table[z]) ----------------
__global__ void k_s0(const int* __restrict__ z, const float* __restrict__ emb) {
    int bi = blockIdx.x;
    int h = threadIdx.x;
    __shared__ float red[4];
    int zz = z[bi];
    float e = emb[zz * HID + h];
    float m = blksum128(e, red) * (1.0f / HID);
    float dx = e - m;
    float var = blksum128(dx * dx, red) * (1.0f / HID);
    g_s0[bi * HID + h] = dx * rsqrtf(var + 1e-5f);
}

// ---------------- K1: geometry + ef-proj (tf32 MMA) + NeighborEmb + 2 fused LN-GEMVs ------
constexpr int EP = 36;  // ef smem pitch (words)
constexpr int GEOM_SMEM = (N * EP + N * (HID / 2)) * 4;  // efS + maskS = 38400 B

__global__ void __launch_bounds__(256) k_geomne(const int* __restrict__ z,
                                                const float* __restrict__ pos,
                                                const float* __restrict__ Wef,
                                                const float* __restrict__ bef,
                                                const float* __restrict__ Ws2v,
                                                const float* __restrict__ bs2v,
                                                const float* __restrict__ Wl0,
                                                const float* __restrict__ bl0) {
    int i = blockIdx.x, b = blockIdx.y;
    int bi = b * N + i;
    int t = threadIdx.x, w = t >> 5, lane = t & 31;
    int gr = lane >> 2, kr = lane & 3;
    extern __shared__ uint32_t gsm[];
    uint32_t* efS = gsm;                 // 96 x EP tf32 bits (aliased later)
    uint32_t* maskS = gsm + N * EP;      // 96 x 64 bf16x2
    float* redA = (float*)efS;           // phase D: 16 x 128 floats
    float* redB = (float*)efS;           // lin passes: 8 x 128
    float* sLin = (float*)efS + 2048;    // 128
    float* oB = (float*)efS + 2048 + 128;  // 128
    __shared__ float eaS[N], evS[3 * N], bS[HID];
    __shared__ float sMean, sRstd;

    if (t < HID) bS[t] = bef[t];
    float padi = (z[bi] != 0) ? 1.0f : 0.0f;
    float xi = pos[bi * 3 + 0];
    float yi = pos[bi * 3 + 1];
    float zi = pos[bi * 3 + 2];

    // Phase A: geometry per j; lane = ef center index
    for (int j = w; j < N; j += 8) {
        float padj = (z[b * N + j] != 0) ? 1.0f : 0.0f;
        float dx = pos[(b * N + j) * 3 + 0] - xi;
        float dy = pos[(b * N + j) * 3 + 1] - yi;
        float dz = pos[(b * N + j) * 3 + 2] - zi;
        float d = sqrtf(dx * dx + dy * dy + dz * dz + 1e-12f);
        float pm = padi * padj * ((i != j) ? 1.0f : 0.0f);
        float ea = (d < CUTOFF) ? 0.5f * (cosf(PI_F * d * (1.0f / CUTOFF)) + 1.0f) * pm : 0.0f;
        float inv = pm / (d + 1e-12f);
        float cc = lane * (CUTOFF / (EF - 1));
        float dd = d - cc;
        float efv = __expf(-RBF_GAMMA * dd * dd) * pm;
        efS[j * EP + lane] = f2tf(efv);
        if (lane == 0) {
            eaS[j] = ea;
            evS[j * 3 + 0] = dx * inv;
            evS[j * 3 + 1] = dy * inv;
            evS[j * 3 + 2] = dz * inv;
            size_t pidx = (size_t)bi * N + j;
            g_ea[pidx] = ea;
            g_ev[pidx * 3 + 0] = dx * inv;
            g_ev[pidx * 3 + 1] = dy * inv;
            g_ev[pidx * 3 + 2] = dz * inv;
        }
    }
    __syncthreads();

    // Phase B: mask_pre = ef(96x32) @ Wef(32x128); warp w owns 16 cols
    {
        int n0 = w * 16;
        float acc[6][2][4];
#pragma unroll
        for (int mt = 0; mt < 6; mt++)
#pragma unroll
            for (int ns = 0; ns < 2; ns++)
#pragma unroll
                for (int c = 0; c < 4; c++) acc[mt][ns][c] = 0.f;
#pragma unroll
        for (int ks = 0; ks < 4; ks++) {
            int k0 = ks * 8;
            uint32_t bc[2][2];
#pragma unroll
            for (int ns = 0; ns < 2; ns++) {
                int col = n0 + ns * 8 + gr;
                bc[ns][0] = f2tf(Wef[(k0 + kr) * HID + col]);
                bc[ns][1] = f2tf(Wef[(k0 + kr + 4) * HID + col]);
            }
#pragma unroll
            for (int mt = 0; mt < 6; mt++) {
                int row = mt * 16 + gr;
                uint32_t a0 = efS[row * EP + k0 + kr];
                uint32_t a1 = efS[(row + 8) * EP + k0 + kr];
                uint32_t a2 = efS[row * EP + k0 + kr + 4];
                uint32_t a3 = efS[(row + 8) * EP + k0 + kr + 4];
#pragma unroll
                for (int ns = 0; ns < 2; ns++)
                    mma8(acc[mt][ns], a0, a1, a2, a3, bc[ns][0], bc[ns][1]);
            }
        }
        // Phase C: epilogue -> maskS (bf16x2)
#pragma unroll
        for (int ns = 0; ns < 2; ns++) {
            int col0 = n0 + ns * 8 + 2 * kr;
            float bv0 = bS[col0], bv1 = bS[col0 + 1];
#pragma unroll
            for (int mt = 0; mt < 6; mt++) {
                int row = mt * 16 + gr;
                float ea0 = eaS[row], ea1 = eaS[row + 8];
                maskS[row * (HID / 2) + (col0 >> 1)] =
                    packbf(silu_f(acc[mt][ns][0] + bv0) * ea0, silu_f(acc[mt][ns][1] + bv1) * ea0);
                maskS[(row + 8) * (HID / 2) + (col0 >> 1)] =
                    packbf(silu_f(acc[mt][ns][2] + bv0) * ea1, silu_f(acc[mt][ns][3] + bv1) * ea1);
            }
        }
    }
    __syncthreads();

    // coalesced mask store to gmem
    for (int idx = t; idx < N * 16; idx += 256) {
        int j = idx >> 4, gq = idx & 15;
        uint4 v = *(const uint4*)&maskS[j * (HID / 2) + gq * 4];
        *(uint4*)&g_maskh[((size_t)bi * N + j) * (HID / 2) + gq * 4] = v;
    }

    // Phase D: neighbor-emb partials (mask from smem, s0 coalesced)
    {
        int hg = t & 15, jr = t >> 4;
        float acc[8];
#pragma unroll
        for (int c = 0; c < 8; c++) acc[c] = 0.f;
#pragma unroll
        for (int j = jr; j < N; j += 16) {
            uint4 mp = *(const uint4*)&maskS[j * (HID / 2) + hg * 4];
            float2 m0 = unpackbf(mp.x), m1 = unpackbf(mp.y), m2 = unpackbf(mp.z), m3 = unpackbf(mp.w);
            const float* s0p = &g_s0[(b * N + j) * HID + hg * 8];
            float4 sa = *(const float4*)s0p;
            float4 sb = *(const float4*)(s0p + 4);
            acc[0] = fmaf(m0.x, sa.x, acc[0]);
            acc[1] = fmaf(m0.y, sa.y, acc[1]);
            acc[2] = fmaf(m1.x, sa.z, acc[2]);
            acc[3] = fmaf(m1.y, sa.w, acc[3]);
            acc[4] = fmaf(m2.x, sb.x, acc[4]);
            acc[5] = fmaf(m2.y, sb.y, acc[5]);
            acc[6] = fmaf(m3.x, sb.z, acc[6]);
            acc[7] = fmaf(m3.y, sb.w, acc[7]);
        }
        __syncthreads();  // efS fully consumed; safe to alias as redA
#pragma unroll
        for (int c = 0; c < 8; c++) redA[jr * HID + hg * 8 + c] = acc[c];
    }
    __syncthreads();
    if (t < HID) {
        float s = g_s0[bi * HID + t];
#pragma unroll
        for (int r = 0; r < 16; r++) s += redA[r * HID + t];
        g_s[bi * HID + t] = s;
        sLin[t] = s;
    }
    __syncthreads();

    // Phase E: two fused LN-GEMVs on s_i: Ws2v -> g_s1, Wl0 -> g_s1b
    int c = t & 31, q = t >> 5;
#pragma unroll
    for (int pass = 0; pass < 2; pass++) {
        const float* W = pass ? Wl0 : Ws2v;
        const float* bb = pass ? bl0 : bs2v;
        float* dst = pass ? g_s1b : g_s1;
        float4 acc = make_float4(0.f, 0.f, 0.f, 0.f);
        int h0 = q * 16;
#pragma unroll
        for (int hh = 0; hh < 16; hh++) {
            int h = h0 + hh;
            float4 wv = *(const float4*)&W[h * HID + c * 4];
            fma4(acc, sLin[h], wv);
        }
        *(float4*)&redB[q * HID + c * 4] = acc;
        __syncthreads();
        if (t < HID) {
            float sum = bb[t];
#pragma unroll
            for (int p = 0; p < 8; p++) sum += redB[p * HID + t];
            oB[t] = sum;
        }
        __syncthreads();
        if (t < 32) {
            float x0 = oB[t], x1 = oB[t + 32], x2 = oB[t + 64], x3 = oB[t + 96];
            float s = x0 + x1 + x2 + x3;
#pragma unroll
            for (int o = 16; o; o >>= 1) s += __shfl_xor_sync(0xffffffffu, s, o);
            float mean = s * (1.0f / HID);
            float q0 = x0 - mean, q1 = x1 - mean, q2 = x2 - mean, q3 = x3 - mean;
            float qq = q0 * q0 + q1 * q1 + q2 * q2 + q3 * q3;
#pragma unroll
            for (int o = 16; o; o >>= 1) qq += __shfl_xor_sync(0xffffffffu, qq, o);
            if (t == 0) {
                sMean = mean;
                sRstd = rsqrtf(qq * (1.0f / HID) + 1e-5f);
            }
        }
        __syncthreads();
        if (t < HID) dst[bi * HID + t] = silu_f((oB[t] - sMean) * sRstd);
        __syncthreads();
    }
}

// ---------------- K2b: fused agg(l) + lin(l+1), 4 atoms/block ----------------
constexpr int LIN_R = 4;
__global__ void __launch_bounds__(256) k_agglin(const float* __restrict__ W,
                                                const float* __restrict__ bv,
                                                int srcsel, int do_lin) {
    __shared__ float sS[LIN_R][HID];
    __shared__ float redS[8][LIN_R][HID];
    __shared__ float oS[LIN_R][HID];
    __shared__ float mS[LIN_R], vSs[LIN_R];
    int t = threadIdx.x, c = t & 31, q = t >> 5;
    int base = blockIdx.x * LIN_R;
    int b = base / N;
    const float* s1src = srcsel ? g_s1b : g_s1;
    float* s1dst = srcsel ? g_s1 : g_s1b;

    // Phase A: agg for 4 atoms
    {
        float4 acc[LIN_R];
#pragma unroll
        for (int r = 0; r < LIN_R; r++) acc[r] = make_float4(0.f, 0.f, 0.f, 0.f);
        for (int j = q; j < N; j += 8) {
            float4 s4 = *(const float4*)&s1src[(b * N + j) * HID + c * 4];
#pragma unroll
            for (int r = 0; r < LIN_R; r++) {
                uint2 mp = *(const uint2*)&g_maskh[((size_t)(base + r) * N + j) * (HID / 2) + c * 2];
                float2 ma = unpackbf(mp.x), mb = unpackbf(mp.y);
                acc[r].x = fmaf(ma.x, s4.x, acc[r].x);
                acc[r].y = fmaf(ma.y, s4.y, acc[r].y);
                acc[r].z = fmaf(mb.x, s4.z, acc[r].z);
                acc[r].w = fmaf(mb.y, s4.w, acc[r].w);
            }
        }
#pragma unroll
        for (int r = 0; r < LIN_R; r++) *(float4*)&redS[q][r][c * 4] = acc[r];
    }
    __syncthreads();
    if (t < 128) {
#pragma unroll
        for (int r = 0; r < LIN_R; r++) {
            float s = g_s[(base + r) * HID + t];
#pragma unroll
            for (int p = 0; p < 8; p++) s += redS[p][r][t];
            sS[r][t] = s;
            g_s[(base + r) * HID + t] = s;
        }
    }
    __syncthreads();
    if (!do_lin) return;

    // Phase B: lin for the same 4 atoms (s already in sS)
    {
        float4 acc[LIN_R];
#pragma unroll
        for (int r = 0; r < LIN_R; r++) acc[r] = make_float4(0.f, 0.f, 0.f, 0.f);
        int h0 = q * 16;
#pragma unroll
        for (int hh = 0; hh < 16; hh++) {
            int h = h0 + hh;
            float4 wv = *(const float4*)&W[h * HID + c * 4];
#pragma unroll
            for (int r = 0; r < LIN_R; r++) fma4(acc[r], sS[r][h], wv);
        }
#pragma unroll
        for (int r = 0; r < LIN_R; r++) *(float4*)&redS[q][r][c * 4] = acc[r];
    }
    __syncthreads();
    if (t < 128) {
#pragma unroll
        for (int r = 0; r < LIN_R; r++) {
            float s = bv[t];
#pragma unroll
            for (int p = 0; p < 8; p++) s += redS[p][r][t];
            oS[r][t] = s;
        }
    }
    __syncthreads();
    if (t < 128) {
        int w = t >> 5, lane = t & 31;
        int r = w;
        float x0 = oS[r][lane], x1 = oS[r][lane + 32], x2 = oS[r][lane + 64], x3 = oS[r][lane + 96];
        float s = x0 + x1 + x2 + x3;
#pragma unroll
        for (int o = 16; o; o >>= 1) s += __shfl_xor_sync(0xffffffffu, s, o);
        float mean = s * (1.0f / HID);
        float q0 = x0 - mean, q1 = x1 - mean, q2 = x2 - mean, q3 = x3 - mean;
        float qq = q0 * q0 + q1 * q1 + q2 * q2 + q3 * q3;
#pragma unroll
        for (int o = 16; o; o >>= 1) qq += __shfl_xor_sync(0xffffffffu, qq, o);
        if (lane == 0) {
            mS[r] = mean;
            vSs[r] = rsqrtf(qq * (1.0f / HID) + 1e-5f);
        }
    }
    __syncthreads();
    if (t < 128) {
#pragma unroll
        for (int r = 0; r < LIN_R; r++) {
            float val = (oS[r][t] - mS[r]) * vSs[r];
            s1dst[(base + r) * HID + t] = silu_f(val);
        }
    }
}

// ---------------- K3: v_i = sum_j mask_ij * s1_j * ev_ij (256 thr) ----------------
__global__ void __launch_bounds__(256) k_v() {
    int i = blockIdx.x, b = blockIdx.y;
    int bi = b * N + i;
    int t = threadIdx.x, c = t & 31, jr = t >> 5;
    __shared__ float4 red[3][8][32];
    float4 a0 = make_float4(0.f, 0.f, 0.f, 0.f), a1 = a0, a2 = a0;
    const uint32_t* mrow = &g_maskh[(size_t)bi * N * (HID / 2) + c * 2];
    const float* evrow = &g_ev[(size_t)bi * N * 3];
#pragma unroll 4
    for (int j = jr; j < N; j += 8) {
        uint2 mp = *(const uint2*)&mrow[(size_t)j * (HID / 2)];
        float2 ma = unpackbf(mp.x), mb = unpackbf(mp.y);
        float4 s4 = *(const float4*)&g_s1[(b * N + j) * HID + c * 4];
        float e0 = evrow[j * 3 + 0], e1 = evrow[j * 3 + 1], e2 = evrow[j * 3 + 2];
        float4 wv;
        wv.x = ma.x * s4.x;
        wv.y = ma.y * s4.y;
        wv.z = mb.x * s4.z;
        wv.w = mb.y * s4.w;
        fma4(a0, e0, wv);
        fma4(a1, e1, wv);
        fma4(a2, e2, wv);
    }
    red[0][jr][c] = a0;
    red[1][jr][c] = a1;
    red[2][jr][c] = a2;
    __syncthreads();
    if (t < 96) {
        int dim = t >> 5;
        float4 s = make_float4(0.f, 0.f, 0.f, 0.f);
#pragma unroll
        for (int r = 0; r < 8; r++) {
            float4 p = red[dim][r][c];
            s.x += p.x;
            s.y += p.y;
            s.z += p.z;
            s.w += p.w;
        }
        *(float4*)&g_v[(bi * 3 + dim) * HID + c * 4] = s;
    }
}

// ---------------- K4: qv/kv, 2 atoms/block ----------------
constexpr int QK_R = 2;
__global__ void __launch_bounds__(128) k_qk4(const float* __restrict__ Wq,
                                             const float* __restrict__ Wk) {
    __shared__ float vS[QK_R][3 * HID];
    __shared__ float redq[4][QK_R][3][HID];
    __shared__ float redk[4][QK_R][3][HID];
    int t = threadIdx.x, c = t & 31, q = t >> 5;
    int base = blockIdx.x * QK_R;
    for (int k = t; k < QK_R * 3 * HID; k += 128) vS[k / (3 * HID)][k % (3 * HID)] = g_v[base * 3 * HID + k];
    __syncthreads();
    float4 aq[QK_R][3], ak[QK_R][3];
#pragma unroll
    for (int r = 0; r < QK_R; r++)
#pragma unroll
        for (int k3 = 0; k3 < 3; k3++) {
            aq[r][k3] = make_float4(0.f, 0.f, 0.f, 0.f);
            ak[r][k3] = make_float4(0.f, 0.f, 0.f, 0.f);
        }
    int h0 = q * 32;
#pragma unroll 4
    for (int hh = 0; hh < 32; hh++) {
        int h = h0 + hh;
        float4 wq = *(const float4*)&Wq[h * HID + c * 4];
        float4 wk = *(const float4*)&Wk[h * HID + c * 4];
#pragma unroll
        for (int r = 0; r < QK_R; r++)
#pragma unroll
            for (int k3 = 0; k3 < 3; k3++) {
                float vv = vS[r][k3 * HID + h];
                fma4(aq[r][k3], vv, wq);
                fma4(ak[r][k3], vv, wk);
            }
    }
#pragma unroll
    for (int r = 0; r < QK_R; r++)
#pragma unroll
        for (int k3 = 0; k3 < 3; k3++) {
            *(float4*)&redq[q][r][k3][c * 4] = aq[r][k3];
            *(float4*)&redk[q][r][k3][c * 4] = ak[r][k3];
        }
    __syncthreads();
    for (int k = t; k < QK_R * 3 * HID; k += 128) {
        int r = k / (3 * HID);
        int rem = k % (3 * HID);
        int k3 = rem / HID, col = rem % HID;
        float sq = redq[0][r][k3][col] + redq[1][r][k3][col] + redq[2][r][k3][col] + redq[3][r][k3][col];
        float sk = redk[0][r][k3][col] + redk[1][r][k3][col] + redk[2][r][k3][col] + redk[3][r][k3][col];
        g_qv[((base + r) * 3 + k3) * HID + col] = sq;
        g_kv[((base + r) * 3 + k3) * HID + col] = sk;
    }
}

// ---------------- K5: fused directional MLP, bf16 mma, depth-2 weight prefetch ----------
constexpr int JH = 48;  // rows per CTA (half tile)
constexpr int PW = 132;
constexpr int SMEM_DIR_BYTES = 2 * JH * PW * 4;  // ~50.7 KB dynamic

__global__ void __launch_bounds__(256) k_dir(const float* __restrict__ bd1,
                                             const float* __restrict__ bd2) {
    int i = blockIdx.x, b = blockIdx.y, half = blockIdx.z;
    int bi = b * N + i;
    int j0 = half * JH;
    int t = threadIdx.x, w = t >> 5, lane = t & 31;
    int gr = lane >> 2, kr = lane & 3;
    extern __shared__ float sm[];
    uint32_t* dirfS = (uint32_t*)sm;      // JH x PW bf16x2
    uint32_t* t1S = dirfS + JH * PW;      // JH x PW bf16x2
    __shared__ float vS[3 * HID], kvS[3 * HID];
    __shared__ float eaS[JH], evS[3 * JH];

    for (int k = t; k < 3 * HID; k += 256) {
        vS[k] = g_v[bi * 3 * HID + k];
        kvS[k] = g_kv[bi * 3 * HID + k];
    }
    if (t < JH) eaS[t] = g_ea[(size_t)bi * N + j0 + t];
    if (t < 3 * JH) evS[t] = g_ev[(size_t)bi * N * 3 + 3 * j0 + t];
    __syncthreads();

    // dirf = concat(dir2, dir3) * ea, packed bf16x2 (h pairs)
    for (int e = t; e < JH * 64; e += 256) {
        int jl = e >> 6, hp = e & 63;
        int h = hp * 2;
        float e0 = evS[jl * 3 + 0], e1 = evS[jl * 3 + 1], e2 = evS[jl * 3 + 2];
        float ea = eaS[jl];
        float d2a = (vS[h] * e0 + vS[HID + h] * e1 + vS[2 * HID + h] * e2) * ea;
        float d2b = (vS[h + 1] * e0 + vS[HID + h + 1] * e1 + vS[2 * HID + h + 1] * e2) * ea;
        const float* qj = &g_qv[(size_t)(b * N + j0 + jl) * 3 * HID + h];
        float d3a = (qj[0] * kvS[h] + qj[HID] * kvS[HID + h] + qj[2 * HID] * kvS[2 * HID + h]) * ea;
        float d3b = (qj[1] * kvS[h + 1] + qj[HID + 1] * kvS[HID + h + 1] +
                     qj[2 * HID + 1] * kvS[2 * HID + h + 1]) * ea;
        dirfS[jl * PW + hp] = packbf(d2a, d2b);
        dirfS[jl * PW + 64 + hp] = packbf(d3a, d3b);
    }
    __syncthreads();

    // phase 3: t1 = silu(dirf(48x256) @ Wd1 + bd1); warp w owns 32 cols
    {
        int n0 = w * 32;
        float acc[3][4][4];
#pragma unroll
        for (int mt = 0; mt < 3; mt++)
#pragma unroll
            for (int ns = 0; ns < 4; ns++)
#pragma unroll
                for (int c = 0; c < 4; c++) acc[mt][ns][c] = 0.f;
        uint32_t bw[2][4][2];
#pragma unroll
        for (int ns = 0; ns < 4; ns++) {
            bw[0][ns][0] = g_W1p[(kr) * 256 + n0 + ns * 8 + gr];
            bw[0][ns][1] = g_W1p[(kr + 4) * 256 + n0 + ns * 8 + gr];
            bw[1][ns][0] = g_W1p[(8 + kr) * 256 + n0 + ns * 8 + gr];
            bw[1][ns][1] = g_W1p[(12 + kr) * 256 + n0 + ns * 8 + gr];
        }
        for (int ks = 0; ks < 16; ks++) {
            int kp0 = ks * 8;
            int sl = ks & 1;
            uint32_t cur[4][2];
#pragma unroll
            for (int ns = 0; ns < 4; ns++) {
                cur[ns][0] = bw[sl][ns][0];
                cur[ns][1] = bw[sl][ns][1];
            }
            if (ks < 14) {
#pragma unroll
                for (int ns = 0; ns < 4; ns++) {
                    bw[sl][ns][0] = g_W1p[(kp0 + 16 + kr) * 256 + n0 + ns * 8 + gr];
                    bw[sl][ns][1] = g_W1p[(kp0 + 20 + kr) * 256 + n0 + ns * 8 + gr];
                }
            }
#pragma unroll
            for (int mt = 0; mt < 3; mt++) {
                int row = mt * 16 + gr;
                uint32_t a0 = dirfS[row * PW + kp0 + kr];
                uint32_t a1 = dirfS[(row + 8) * PW + kp0 + kr];
                uint32_t a2 = dirfS[row * PW + kp0 + kr + 4];
                uint32_t a3 = dirfS[(row + 8) * PW + kp0 + kr + 4];
#pragma unroll
                for (int ns = 0; ns < 4; ns++)
                    mma16(acc[mt][ns], a0, a1, a2, a3, cur[ns][0], cur[ns][1]);
            }
        }
#pragma unroll
        for (int ns = 0; ns < 4; ns++) {
            int col0 = n0 + ns * 8 + 2 * kr;
            float bv0 = bd1[col0], bv1 = bd1[col0 + 1];
            int wp = (col0 >> 1);
#pragma unroll
            for (int mt = 0; mt < 3; mt++) {
                int row = mt * 16 + gr;
                t1S[row * PW + wp] = packbf(silu_f(acc[mt][ns][0] + bv0), silu_f(acc[mt][ns][1] + bv1));
                t1S[(row + 8) * PW + wp] = packbf(silu_f(acc[mt][ns][2] + bv0), silu_f(acc[mt][ns][3] + bv1));
            }
        }
    }
    __syncthreads();

    // phase 4: dp = silu(t1(48x256) @ Wd2 + bd2); mask(bf16) *= dp; warp owns 16 cols
    {
        int n0 = w * 16;
        float acc[3][2][4];
#pragma unroll
        for (int mt = 0; mt < 3; mt++)
#pragma unroll
            for (int ns = 0; ns < 2; ns++)
#pragma unroll
                for (int c = 0; c < 4; c++) acc[mt][ns][c] = 0.f;
        uint32_t bw[2][2][2];
#pragma unroll
        for (int ns = 0; ns < 2; ns++) {
            bw[0][ns][0] = g_W2p[(kr) * 128 + n0 + ns * 8 + gr];
            bw[0][ns][1] = g_W2p[(kr + 4) * 128 + n0 + ns * 8 + gr];
            bw[1][ns][0] = g_W2p[(8 + kr) * 128 + n0 + ns * 8 + gr];
            bw[1][ns][1] = g_W2p[(12 + kr) * 128 + n0 + ns * 8 + gr];
        }
        for (int ks = 0; ks < 16; ks++) {
            int kp0 = ks * 8;
            int sl = ks & 1;
            uint32_t cur[2][2];
#pragma unroll
            for (int ns = 0; ns < 2; ns++) {
                cur[ns][0] = bw[sl][ns][0];
                cur[ns][1] = bw[sl][ns][1];
            }
            if (ks < 14) {
#pragma unroll
                for (int ns = 0; ns < 2; ns++) {
                    bw[sl][ns][0] = g_W2p[(kp0 + 16 + kr) * 128 + n0 + ns * 8 + gr];
                    bw[sl][ns][1] = g_W2p[(kp0 + 20 + kr) * 128 + n0 + ns * 8 + gr];
                }
            }
#pragma unroll
            for (int mt = 0; mt < 3; mt++) {
                int row = mt * 16 + gr;
                uint32_t a0 = t1S[row * PW + kp0 + kr];
                uint32_t a1 = t1S[(row + 8) * PW + kp0 + kr];
                uint32_t a2 = t1S[row * PW + kp0 + kr + 4];
                uint32_t a3 = t1S[(row + 8) * PW + kp0 + kr + 4];
#pragma unroll
                for (int ns = 0; ns < 2; ns++)
                    mma16(acc[mt][ns], a0, a1, a2, a3, cur[ns][0], cur[ns][1]);
            }
        }
#pragma unroll
        for (int ns = 0; ns < 2; ns++) {
            int col0 = n0 + ns * 8 + 2 * kr;
            float bv0 = bd2[col0], bv1 = bd2[col0 + 1];
#pragma unroll
            for (int mt = 0; mt < 3; mt++) {
                int row = mt * 16 + gr;
                size_t idx0 = ((size_t)bi * N + j0 + row) * (HID / 2) + (col0 >> 1);
                float2 m0 = unpackbf(g_maskh[idx0]);
                g_maskh[idx0] = packbf(m0.x * silu_f(acc[mt][ns][0] + bv0),
                                       m0.y * silu_f(acc[mt][ns][1] + bv1));
                size_t idx1 = ((size_t)bi * N + j0 + row + 8) * (HID / 2) + (col0 >> 1);
                float2 m1 = unpackbf(g_maskh[idx1]);
                g_maskh[idx1] = packbf(m1.x * silu_f(acc[mt][ns][2] + bv0),
                                       m1.y * silu_f(acc[mt][ns][3] + bv1));
            }
        }
    }
}

// ---------------- K7: readout ----------------
__global__ void k_read(const int* __restrict__ z, const float* __restrict__ Wout,
                       const float* __restrict__ bout, float* __restrict__ out) {
    int b = blockIdx.x;
    int h = threadIdx.x;
    __shared__ float red[4];
    float acc = 0.0f;
    for (int i = 0; i < N; i++) {
        if (z[b * N + i] != 0) acc += g_s[(b * N + i) * HID + h];
    }
    float p = acc * Wout[h];
    float s = blksum128(p, red);
    if (h == 0) out[b] = s + bout[0];
}

// ---------------- launch ----------------
extern "C" void kernel_launch(void* const* d_in, const int* in_sizes, int n_in,
                              void* d_out, int out_size) {
    const int* z = (const int*)d_in[0];
    const float* pos = (const float*)d_in[1];
    const float* emb = (const float*)d_in[2];
    const float* Wef = (const float*)d_in[3];
    const float* bef = (const float*)d_in[4];
    const float* Ws2v = (const float*)d_in[5];
    const float* bs2v = (const float*)d_in[6];
    const float* Wq = (const float*)d_in[7];
    const float* Wk = (const float*)d_in[8];
    const float* Wd1 = (const float*)d_in[9];
    const float* bd1 = (const float*)d_in[10];
    const float* Wd2 = (const float*)d_in[11];
    const float* bd2 = (const float*)d_in[12];
    const float* Wint = (const float*)d_in[13];
    const float* bint = (const float*)d_in[14];
    const float* Wout = (const float*)d_in[15];
    const float* bout = (const float*)d_in[16];
    float* out = (float*)d_out;

    cudaFuncSetAttribute(k_dir, cudaFuncAttributeMaxDynamicSharedMemorySize, SMEM_DIR_BYTES);
    cudaFuncSetAttribute(k_geomne, cudaFuncAttributeMaxDynamicSharedMemorySize, GEOM_SMEM);

    dim3 g(N, B);
    dim3 gd(N, B, 2);
    k_prep<<<(128 * 256 + 128 * 128 + 255) / 256, 256>>>(Wd1, Wd2);
    k_s0<<<BN, 128>>>(z, emb);
    // geomne also computes s1(s2v) -> g_s1 and s1(layer0) -> g_s1b
    k_geomne<<<g, 256, GEOM_SMEM>>>(z, pos, Wef, bef, Ws2v, bs2v, Wint, bint);
    k_v<<<g, 256>>>();
    k_qk4<<<BN / QK_R, 128>>>(Wq, Wk);
    k_dir<<<gd, 256, SMEM_DIR_BYTES>>>(bd1, bd2);
    // message-passing: lin0 output already in g_s1b
    k_agglin<<<BN / LIN_R, 256>>>(Wint + 1 * HID * HID, bint + 1 * HID, 1, 1);  // agg0(src s1b) + lin1 -> g_s1
    k_agglin<<<BN / LIN_R, 256>>>(Wint + 2 * HID * HID, bint + 2 * HID, 0, 1);  // agg1(src s1) + lin2 -> g_s1b
    k_agglin<<<BN / LIN_R, 256>>>(Wint + 3 * HID * HID, bint + 3 * HID, 1, 1);  // agg2(src s1b) + lin3 -> g_s1
    k_agglin<<<BN / LIN_R, 256>>>(Wint, bint, 0, 0);                            // agg3(src s1) only
    k_read<<<B, 128>>>(z, Wout, bout, out);
}

// round 16
// speedup vs baseline: 1.0734x; 1.0734x over previous
#include <cuda_runtime.h>
#include <cuda_bf16.h>
#include <cstdint>
#include <cstddef>

#define DEVFN __device__ __forceinline__

constexpr int B = 16, N = 96, HID = 128, EF = 32, L = 4;
constexpr int BN = B * N;
constexpr float CUTOFF = 10.0f, RBF_GAMMA = 10.0f;
constexpr float PI_F = 3.14159265358979323846f;

// ---------------- scratch (device globals) ----------------
__device__ uint32_t g_maskh[(size_t)BN * N * (HID / 2)];  // bf16x2 mask
__device__ float g_s0[BN * HID];
__device__ float g_s[BN * HID];
__device__ float g_s1[BN * HID];
__device__ float g_s1b[BN * HID];
__device__ float g_v[BN * 3 * HID];
__device__ float g_qv[BN * 3 * HID];
__device__ float g_kv[BN * 3 * HID];
__device__ float g_ea[BN * N];
__device__ float g_ev[BN * N * 3];
__device__ uint32_t g_W1p[128 * 256];  // Wd1 packed bf16x2 (k-pairs)
__device__ uint32_t g_W2p[128 * 128];  // Wd2 packed bf16x2

DEVFN float silu_f(float x) { return x / (1.0f + __expf(-x)); }

DEVFN void fma4(float4& a, float x, const float4 w) {
    a.x = fmaf(x, w.x, a.x);
    a.y = fmaf(x, w.y, a.y);
    a.z = fmaf(x, w.z, a.z);
    a.w = fmaf(x, w.w, a.w);
}

DEVFN uint32_t packbf(float lo, float hi) {
    uint32_t r;
    asm("cvt.rn.bf16x2.f32 %0, %1, %2;" : "=r"(r) : "f"(hi), "f"(lo));
    return r;
}
DEVFN float2 unpackbf(uint32_t u) {
    __nv_bfloat162 b = *reinterpret_cast<__nv_bfloat162*>(&u);
    return __bfloat1622float2(b);
}

DEVFN uint32_t f2tf(float x) {
    uint32_t r;
    asm("cvt.rna.tf32.f32 %0, %1;" : "=r"(r) : "f"(x));
    return r;
}

DEVFN void mma16(float c[4], uint32_t a0, uint32_t a1, uint32_t a2, uint32_t a3,
                 uint32_t b0, uint32_t b1) {
    asm volatile(
        "mma.sync.aligned.m16n8k16.row.col.f32.bf16.bf16.f32 "
        "{%0,%1,%2,%3},{%4,%5,%6,%7},{%8,%9},{%0,%1,%2,%3};\n"
        : "+f"(c[0]), "+f"(c[1]), "+f"(c[2]), "+f"(c[3])
        : "r"(a0), "r"(a1), "r"(a2), "r"(a3), "r"(b0), "r"(b1));
}

DEVFN void mma8(float c[4], uint32_t a0, uint32_t a1, uint32_t a2, uint32_t a3,
                uint32_t b0, uint32_t b1) {
    asm volatile(
        "mma.sync.aligned.m16n8k8.row.col.f32.tf32.tf32.f32 "
        "{%0,%1,%2,%3},{%4,%5,%6,%7},{%8,%9},{%0,%1,%2,%3};\n"
        : "+f"(c[0]), "+f"(c[1]), "+f"(c[2]), "+f"(c[3])
        : "r"(a0), "r"(a1), "r"(a2), "r"(a3), "r"(b0), "r"(b1));
}

DEVFN float blksum128(float v, float* red) {
#pragma unroll
    for (int o = 16; o; o >>= 1) v += __shfl_xor_sync(0xffffffffu, v, o);
    if ((threadIdx.x & 31) == 0) red[threadIdx.x >> 5] = v;
    __syncthreads();
    float r = red[0] + red[1] + red[2] + red[3];
    __syncthreads();
    return r;
}

// ---------------- K0: merged s0-LayerNorm + Wd1/Wd2 packing ----------------
// blocks [0, BN): s0 = LN(emb[z]); blocks [BN, BN+160): pack weights
__global__ void __launch_bounds__(128) k_init(const int* __restrict__ z,
                                              const float* __restrict__ emb,
                                              const float* __restrict__ Wd1,
                                              const float* __restrict__ Wd2) {
    int blk = blockIdx.x;
    if (blk < BN) {
        int bi = blk;
        int h = threadIdx.x;
        __shared__ float red[4];
        int zz = z[bi];
        float e = emb[zz * HID + h];
        float m = blksum128(e, red) * (1.0f / HID);
        float dx = e - m;
        float var = blksum128(dx * dx, red) * (1.0f / HID);
        g_s0[bi * HID + h] = dx * rsqrtf(var + 1e-5f);
    } else {
        int idx = (blk - BN) * 128 + threadIdx.x;
        int tot = idx * 2;  // each thread packs 2 entries (stride layout)
        for (int u = tot; u < tot + 2; u++) {
            if (u < 128 * 256) {
                int kp = u >> 8, n = u & 255;
                g_W1p[u] = packbf(Wd1[(2 * kp) * 256 + n], Wd1[(2 * kp + 1) * 256 + n]);
            } else {
                int r = u - 128 * 256;
                if (r < 128 * 128) {
                    int kp = r >> 7, n = r & 127;
                    g_W2p[r] = packbf(Wd2[(2 * kp) * 128 + n], Wd2[(2 * kp + 1) * 128 + n]);
                }
            }
        }
    }
}
constexpr int INIT_BLKS = BN + (128 * 256 + 128 * 128) / 256;  // 1536 + 192

// ---------------- K1: geometry + ef-proj via tf32 MMA -> mask(bf16), fused NeighborEmb ----
constexpr int EP = 36;  // ef smem pitch (words)
constexpr int GEOM_SMEM = (N * EP + N * (HID / 2)) * 4;  // efS + maskS = 38400 B

__global__ void __launch_bounds__(256) k_geomne(const int* __restrict__ z,
                                                const float* __restrict__ pos,
                                                const float* __restrict__ Wef,
                                                const float* __restrict__ bef) {
    int i = blockIdx.x, b = blockIdx.y;
    int bi = b * N + i;
    int t = threadIdx.x, w = t >> 5, lane = t & 31;
    int gr = lane >> 2, kr = lane & 3;
    extern __shared__ uint32_t gsm[];
    uint32_t* efS = gsm;                 // 96 x EP tf32 bits (aliased later)
    uint32_t* maskS = gsm + N * EP;      // 96 x 64 bf16x2
    float* redA = (float*)efS;           // phase D: 16 x 128 floats
    __shared__ float eaS[N], evS[3 * N], bS[HID];

    if (t < HID) bS[t] = bef[t];
    float padi = (z[bi] != 0) ? 1.0f : 0.0f;
    float xi = pos[bi * 3 + 0];
    float yi = pos[bi * 3 + 1];
    float zi = pos[bi * 3 + 2];

    // Phase A: geometry per j; lane = ef center index
    for (int j = w; j < N; j += 8) {
        float padj = (z[b * N + j] != 0) ? 1.0f : 0.0f;
        float dx = pos[(b * N + j) * 3 + 0] - xi;
        float dy = pos[(b * N + j) * 3 + 1] - yi;
        float dz = pos[(b * N + j) * 3 + 2] - zi;
        float d = sqrtf(dx * dx + dy * dy + dz * dz + 1e-12f);
        float pm = padi * padj * ((i != j) ? 1.0f : 0.0f);
        float ea = (d < CUTOFF) ? 0.5f * (cosf(PI_F * d * (1.0f / CUTOFF)) + 1.0f) * pm : 0.0f;
        float inv = pm / (d + 1e-12f);
        float cc = lane * (CUTOFF / (EF - 1));
        float dd = d - cc;
        float efv = __expf(-RBF_GAMMA * dd * dd) * pm;
        efS[j * EP + lane] = f2tf(efv);
        if (lane == 0) {
            eaS[j] = ea;
            evS[j * 3 + 0] = dx * inv;
            evS[j * 3 + 1] = dy * inv;
            evS[j * 3 + 2] = dz * inv;
            size_t pidx = (size_t)bi * N + j;
            g_ea[pidx] = ea;
            g_ev[pidx * 3 + 0] = dx * inv;
            g_ev[pidx * 3 + 1] = dy * inv;
            g_ev[pidx * 3 + 2] = dz * inv;
        }
    }
    __syncthreads();

    // Phase B: mask_pre = ef(96x32) @ Wef(32x128); warp w owns 16 cols
    {
        int n0 = w * 16;
        float acc[6][2][4];
#pragma unroll
        for (int mt = 0; mt < 6; mt++)
#pragma unroll
            for (int ns = 0; ns < 2; ns++)
#pragma unroll
                for (int c = 0; c < 4; c++) acc[mt][ns][c] = 0.f;
#pragma unroll
        for (int ks = 0; ks < 4; ks++) {
            int k0 = ks * 8;
            uint32_t bc[2][2];
#pragma unroll
            for (int ns = 0; ns < 2; ns++) {
                int col = n0 + ns * 8 + gr;
                bc[ns][0] = f2tf(Wef[(k0 + kr) * HID + col]);
                bc[ns][1] = f2tf(Wef[(k0 + kr + 4) * HID + col]);
            }
#pragma unroll
            for (int mt = 0; mt < 6; mt++) {
                int row = mt * 16 + gr;
                uint32_t a0 = efS[row * EP + k0 + kr];
                uint32_t a1 = efS[(row + 8) * EP + k0 + kr];
                uint32_t a2 = efS[row * EP + k0 + kr + 4];
                uint32_t a3 = efS[(row + 8) * EP + k0 + kr + 4];
#pragma unroll
                for (int ns = 0; ns < 2; ns++)
                    mma8(acc[mt][ns], a0, a1, a2, a3, bc[ns][0], bc[ns][1]);
            }
        }
        // Phase C: epilogue -> maskS (bf16x2)
#pragma unroll
        for (int ns = 0; ns < 2; ns++) {
            int col0 = n0 + ns * 8 + 2 * kr;
            float bv0 = bS[col0], bv1 = bS[col0 + 1];
#pragma unroll
            for (int mt = 0; mt < 6; mt++) {
                int row = mt * 16 + gr;
                float ea0 = eaS[row], ea1 = eaS[row + 8];
                maskS[row * (HID / 2) + (col0 >> 1)] =
                    packbf(silu_f(acc[mt][ns][0] + bv0) * ea0, silu_f(acc[mt][ns][1] + bv1) * ea0);
                maskS[(row + 8) * (HID / 2) + (col0 >> 1)] =
                    packbf(silu_f(acc[mt][ns][2] + bv0) * ea1, silu_f(acc[mt][ns][3] + bv1) * ea1);
            }
        }
    }
    __syncthreads();

    // coalesced mask store to gmem
    for (int idx = t; idx < N * 16; idx += 256) {
        int j = idx >> 4, gq = idx & 15;
        uint4 v = *(const uint4*)&maskS[j * (HID / 2) + gq * 4];
        *(uint4*)&g_maskh[((size_t)bi * N + j) * (HID / 2) + gq * 4] = v;
    }

    // Phase D: neighbor-emb partials (mask from smem, s0 coalesced)
    {
        int hg = t & 15, jr = t >> 4;
        float acc[8];
#pragma unroll
        for (int c = 0; c < 8; c++) acc[c] = 0.f;
#pragma unroll
        for (int j = jr; j < N; j += 16) {
            uint4 mp = *(const uint4*)&maskS[j * (HID / 2) + hg * 4];
            float2 m0 = unpackbf(mp.x), m1 = unpackbf(mp.y), m2 = unpackbf(mp.z), m3 = unpackbf(mp.w);
            const float* s0p = &g_s0[(b * N + j) * HID + hg * 8];
            float4 sa = *(const float4*)s0p;
            float4 sb = *(const float4*)(s0p + 4);
            acc[0] = fmaf(m0.x, sa.x, acc[0]);
            acc[1] = fmaf(m0.y, sa.y, acc[1]);
            acc[2] = fmaf(m1.x, sa.z, acc[2]);
            acc[3] = fmaf(m1.y, sa.w, acc[3]);
            acc[4] = fmaf(m2.x, sb.x, acc[4]);
            acc[5] = fmaf(m2.y, sb.y, acc[5]);
            acc[6] = fmaf(m3.x, sb.z, acc[6]);
            acc[7] = fmaf(m3.y, sb.w, acc[7]);
        }
        __syncthreads();  // efS fully consumed; safe to alias as redA
#pragma unroll
        for (int c = 0; c < 8; c++) redA[jr * HID + hg * 8 + c] = acc[c];
    }
    __syncthreads();
    if (t < HID) {
        float s = g_s0[bi * HID + t];
#pragma unroll
        for (int r = 0; r < 16; r++) s += redA[r * HID + t];
        g_s[bi * HID + t] = s;
    }
}

// ---------------- K2: s1 = silu(LN(s @ W + b)), 4 atoms/block, 256 threads ----------------
constexpr int LIN_R = 4;
__global__ void __launch_bounds__(256) k_lin4(const float* __restrict__ W,
                                              const float* __restrict__ bv) {
    __shared__ float sS[LIN_R][HID];
    __shared__ float redS[8][LIN_R][HID];
    __shared__ float oS[LIN_R][HID];
    __shared__ float mS[LIN_R], vSs[LIN_R];
    int t = threadIdx.x, c = t & 31, q = t >> 5;
    int base = blockIdx.x * LIN_R;
    for (int k = t; k < LIN_R * HID; k += 256) sS[k >> 7][k & 127] = g_s[base * HID + k];
    __syncthreads();
    float4 acc[LIN_R];
#pragma unroll
    for (int r = 0; r < LIN_R; r++) acc[r] = make_float4(0.f, 0.f, 0.f, 0.f);
    int h0 = q * 16;
#pragma unroll
    for (int hh = 0; hh < 16; hh++) {
        int h = h0 + hh;
        float4 wv = *(const float4*)&W[h * HID + c * 4];
#pragma unroll
        for (int r = 0; r < LIN_R; r++) fma4(acc[r], sS[r][h], wv);
    }
#pragma unroll
    for (int r = 0; r < LIN_R; r++) *(float4*)&redS[q][r][c * 4] = acc[r];
    __syncthreads();
    if (t < 128) {
#pragma unroll
        for (int r = 0; r < LIN_R; r++) {
            float s = bv[t];
#pragma unroll
            for (int p = 0; p < 8; p++) s += redS[p][r][t];
            oS[r][t] = s;
        }
    }
    __syncthreads();
    if (t < 128) {
        int w = t >> 5, lane = t & 31;
        int r = w;
        float x0 = oS[r][lane], x1 = oS[r][lane + 32], x2 = oS[r][lane + 64], x3 = oS[r][lane + 96];
        float s = x0 + x1 + x2 + x3;
#pragma unroll
        for (int o = 16; o; o >>= 1) s += __shfl_xor_sync(0xffffffffu, s, o);
        float mean = s * (1.0f / HID);
        float q0 = x0 - mean, q1 = x1 - mean, q2 = x2 - mean, q3 = x3 - mean;
        float qq = q0 * q0 + q1 * q1 + q2 * q2 + q3 * q3;
#pragma unroll
        for (int o = 16; o; o >>= 1) qq += __shfl_xor_sync(0xffffffffu, qq, o);
        if (lane == 0) {
            mS[r] = mean;
            vSs[r] = rsqrtf(qq * (1.0f / HID) + 1e-5f);
        }
    }
    __syncthreads();
    if (t < 128) {
#pragma unroll
        for (int r = 0; r < LIN_R; r++) {
            float val = (oS[r][t] - mS[r]) * vSs[r];
            g_s1[(base + r) * HID + t] = silu_f(val);
        }
    }
}

// ---------------- K2b: fused agg(l) + lin(l+1), 4 atoms/block ----------------
__global__ void __launch_bounds__(256) k_agglin(const float* __restrict__ W,
                                                const float* __restrict__ bv,
                                                int srcsel, int do_lin) {
    __shared__ float sS[LIN_R][HID];
    __shared__ float redS[8][LIN_R][HID];
    __shared__ float oS[LIN_R][HID];
    __shared__ float mS[LIN_R], vSs[LIN_R];
    int t = threadIdx.x, c = t & 31, q = t >> 5;
    int base = blockIdx.x * LIN_R;
    int b = base / N;
    const float* s1src = srcsel ? g_s1b : g_s1;
    float* s1dst = srcsel ? g_s1 : g_s1b;

    // Phase A: agg for 4 atoms
    {
        float4 acc[LIN_R];
#pragma unroll
        for (int r = 0; r < LIN_R; r++) acc[r] = make_float4(0.f, 0.f, 0.f, 0.f);
        for (int j = q; j < N; j += 8) {
            float4 s4 = *(const float4*)&s1src[(b * N + j) * HID + c * 4];
#pragma unroll
            for (int r = 0; r < LIN_R; r++) {
                uint2 mp = *(const uint2*)&g_maskh[((size_t)(base + r) * N + j) * (HID / 2) + c * 2];
                float2 ma = unpackbf(mp.x), mb = unpackbf(mp.y);
                acc[r].x = fmaf(ma.x, s4.x, acc[r].x);
                acc[r].y = fmaf(ma.y, s4.y, acc[r].y);
                acc[r].z = fmaf(mb.x, s4.z, acc[r].z);
                acc[r].w = fmaf(mb.y, s4.w, acc[r].w);
            }
        }
#pragma unroll
        for (int r = 0; r < LIN_R; r++) *(float4*)&redS[q][r][c * 4] = acc[r];
    }
    __syncthreads();
    if (t < 128) {
#pragma unroll
        for (int r = 0; r < LIN_R; r++) {
            float s = g_s[(base + r) * HID + t];
#pragma unroll
            for (int p = 0; p < 8; p++) s += redS[p][r][t];
            sS[r][t] = s;
            g_s[(base + r) * HID + t] = s;
        }
    }
    __syncthreads();
    if (!do_lin) return;

    // Phase B: lin for the same 4 atoms (s already in sS)
    {
        float4 acc[LIN_R];
#pragma unroll
        for (int r = 0; r < LIN_R; r++) acc[r] = make_float4(0.f, 0.f, 0.f, 0.f);
        int h0 = q * 16;
#pragma unroll
        for (int hh = 0; hh < 16; hh++) {
            int h = h0 + hh;
            float4 wv = *(const float4*)&W[h * HID + c * 4];
#pragma unroll
            for (int r = 0; r < LIN_R; r++) fma4(acc[r], sS[r][h], wv);
        }
#pragma unroll
        for (int r = 0; r < LIN_R; r++) *(float4*)&redS[q][r][c * 4] = acc[r];
    }
    __syncthreads();
    if (t < 128) {
#pragma unroll
        for (int r = 0; r < LIN_R; r++) {
            float s = bv[t];
#pragma unroll
            for (int p = 0; p < 8; p++) s += redS[p][r][t];
            oS[r][t] = s;
        }
    }
    __syncthreads();
    if (t < 128) {
        int w = t >> 5, lane = t & 31;
        int r = w;
        float x0 = oS[r][lane], x1 = oS[r][lane + 32], x2 = oS[r][lane + 64], x3 = oS[r][lane + 96];
        float s = x0 + x1 + x2 + x3;
#pragma unroll
        for (int o = 16; o; o >>= 1) s += __shfl_xor_sync(0xffffffffu, s, o);
        float mean = s * (1.0f / HID);
        float q0 = x0 - mean, q1 = x1 - mean, q2 = x2 - mean, q3 = x3 - mean;
        float qq = q0 * q0 + q1 * q1 + q2 * q2 + q3 * q3;
#pragma unroll
        for (int o = 16; o; o >>= 1) qq += __shfl_xor_sync(0xffffffffu, qq, o);
        if (lane == 0) {
            mS[r] = mean;
            vSs[r] = rsqrtf(qq * (1.0f / HID) + 1e-5f);
        }
    }
    __syncthreads();
    if (t < 128) {
#pragma unroll
        for (int r = 0; r < LIN_R; r++) {
            float val = (oS[r][t] - mS[r]) * vSs[r];
            s1dst[(base + r) * HID + t] = silu_f(val);
        }
    }
}

// ---------------- K3: v_i = sum_j mask_ij * s1_j * ev_ij (256 thr) ----------------
__global__ void __launch_bounds__(256) k_v() {
    int i = blockIdx.x, b = blockIdx.y;
    int bi = b * N + i;
    int t = threadIdx.x, c = t & 31, jr = t >> 5;
    __shared__ float4 red[3][8][32];
    float4 a0 = make_float4(0.f, 0.f, 0.f, 0.f), a1 = a0, a2 = a0;
    const uint32_t* mrow = &g_maskh[(size_t)bi * N * (HID / 2) + c * 2];
    const float* evrow = &g_ev[(size_t)bi * N * 3];
#pragma unroll 4
    for (int j = jr; j < N; j += 8) {
        uint2 mp = *(const uint2*)&mrow[(size_t)j * (HID / 2)];
        float2 ma = unpackbf(mp.x), mb = unpackbf(mp.y);
        float4 s4 = *(const float4*)&g_s1[(b * N + j) * HID + c * 4];
        float e0 = evrow[j * 3 + 0], e1 = evrow[j * 3 + 1], e2 = evrow[j * 3 + 2];
        float4 wv;
        wv.x = ma.x * s4.x;
        wv.y = ma.y * s4.y;
        wv.z = mb.x * s4.z;
        wv.w = mb.y * s4.w;
        fma4(a0, e0, wv);
        fma4(a1, e1, wv);
        fma4(a2, e2, wv);
    }
    red[0][jr][c] = a0;
    red[1][jr][c] = a1;
    red[2][jr][c] = a2;
    __syncthreads();
    if (t < 96) {
        int dim = t >> 5;
        float4 s = make_float4(0.f, 0.f, 0.f, 0.f);
#pragma unroll
        for (int r = 0; r < 8; r++) {
            float4 p = red[dim][r][c];
            s.x += p.x;
            s.y += p.y;
            s.z += p.z;
            s.w += p.w;
        }
        *(float4*)&g_v[(bi * 3 + dim) * HID + c * 4] = s;
    }
}

// ---------------- K4: qv/kv, 2 atoms/block ----------------
constexpr int QK_R = 2;
__global__ void __launch_bounds__(128) k_qk4(const float* __restrict__ Wq,
                                             const float* __restrict__ Wk) {
    __shared__ float vS[QK_R][3 * HID];
    __shared__ float redq[4][QK_R][3][HID];
    __shared__ float redk[4][QK_R][3][HID];
    int t = threadIdx.x, c = t & 31, q = t >> 5;
    int base = blockIdx.x * QK_R;
    for (int k = t; k < QK_R * 3 * HID; k += 128) vS[k / (3 * HID)][k % (3 * HID)] = g_v[base * 3 * HID + k];
    __syncthreads();
    float4 aq[QK_R][3], ak[QK_R][3];
#pragma unroll
    for (int r = 0; r < QK_R; r++)
#pragma unroll
        for (int k3 = 0; k3 < 3; k3++) {
            aq[r][k3] = make_float4(0.f, 0.f, 0.f, 0.f);
            ak[r][k3] = make_float4(0.f, 0.f, 0.f, 0.f);
        }
    int h0 = q * 32;
#pragma unroll 4
    for (int hh = 0; hh < 32; hh++) {
        int h = h0 + hh;
        float4 wq = *(const float4*)&Wq[h * HID + c * 4];
        float4 wk = *(const float4*)&Wk[h * HID + c * 4];
#pragma unroll
        for (int r = 0; r < QK_R; r++)
#pragma unroll
            for (int k3 = 0; k3 < 3; k3++) {
                float vv = vS[r][k3 * HID + h];
                fma4(aq[r][k3], vv, wq);
                fma4(ak[r][k3], vv, wk);
            }
    }
#pragma unroll
    for (int r = 0; r < QK_R; r++)
#pragma unroll
        for (int k3 = 0; k3 < 3; k3++) {
            *(float4*)&redq[q][r][k3][c * 4] = aq[r][k3];
            *(float4*)&redk[q][r][k3][c * 4] = ak[r][k3];
        }
    __syncthreads();
    for (int k = t; k < QK_R * 3 * HID; k += 128) {
        int r = k / (3 * HID);
        int rem = k % (3 * HID);
        int k3 = rem / HID, col = rem % HID;
        float sq = redq[0][r][k3][col] + redq[1][r][k3][col] + redq[2][r][k3][col] + redq[3][r][k3][col];
        float sk = redk[0][r][k3][col] + redk[1][r][k3][col] + redk[2][r][k3][col] + redk[3][r][k3][col];
        g_qv[((base + r) * 3 + k3) * HID + col] = sq;
        g_kv[((base + r) * 3 + k3) * HID + col] = sk;
    }
}

// ---------------- K5: fused directional MLP, bf16 mma, depth-2 weight prefetch ----------
constexpr int JH = 48;  // rows per CTA (half tile)
constexpr int PW = 132;
constexpr int SMEM_DIR_BYTES = 2 * JH * PW * 4;  // ~50.7 KB dynamic

__global__ void __launch_bounds__(256) k_dir(const float* __restrict__ bd1,
                                             const float* __restrict__ bd2) {
    int i = blockIdx.x, b = blockIdx.y, half = blockIdx.z;
    int bi = b * N + i;
    int j0 = half * JH;
    int t = threadIdx.x, w = t >> 5, lane = t & 31;
    int gr = lane >> 2, kr = lane & 3;
    extern __shared__ float sm[];
    uint32_t* dirfS = (uint32_t*)sm;      // JH x PW bf16x2
    uint32_t* t1S = dirfS + JH * PW;      // JH x PW bf16x2
    __shared__ float vS[3 * HID], kvS[3 * HID];
    __shared__ float eaS[JH], evS[3 * JH];

    for (int k = t; k < 3 * HID; k += 256) {
        vS[k] = g_v[bi * 3 * HID + k];
        kvS[k] = g_kv[bi * 3 * HID + k];
    }
    if (t < JH) eaS[t] = g_ea[(size_t)bi * N + j0 + t];
    if (t < 3 * JH) evS[t] = g_ev[(size_t)bi * N * 3 + 3 * j0 + t];
    __syncthreads();

    // dirf = concat(dir2, dir3) * ea, packed bf16x2 (h pairs)
    for (int e = t; e < JH * 64; e += 256) {
        int jl = e >> 6, hp = e & 63;
        int h = hp * 2;
        float e0 = evS[jl * 3 + 0], e1 = evS[jl * 3 + 1], e2 = evS[jl * 3 + 2];
        float ea = eaS[jl];
        float d2a = (vS[h] * e0 + vS[HID + h] * e1 + vS[2 * HID + h] * e2) * ea;
        float d2b = (vS[h + 1] * e0 + vS[HID + h + 1] * e1 + vS[2 * HID + h + 1] * e2) * ea;
        const float* qj = &g_qv[(size_t)(b * N + j0 + jl) * 3 * HID + h];
        float d3a = (qj[0] * kvS[h] + qj[HID] * kvS[HID + h] + qj[2 * HID] * kvS[2 * HID + h]) * ea;
        float d3b = (qj[1] * kvS[h + 1] + qj[HID + 1] * kvS[HID + h + 1] +
                     qj[2 * HID + 1] * kvS[2 * HID + h + 1]) * ea;
        dirfS[jl * PW + hp] = packbf(d2a, d2b);
        dirfS[jl * PW + 64 + hp] = packbf(d3a, d3b);
    }
    __syncthreads();

    // phase 3: t1 = silu(dirf(48x256) @ Wd1 + bd1); warp w owns 32 cols
    {
        int n0 = w * 32;
        float acc[3][4][4];
#pragma unroll
        for (int mt = 0; mt < 3; mt++)
#pragma unroll
            for (int ns = 0; ns < 4; ns++)
#pragma unroll
                for (int c = 0; c < 4; c++) acc[mt][ns][c] = 0.f;
        uint32_t bw[2][4][2];
#pragma unroll
        for (int ns = 0; ns < 4; ns++) {
            bw[0][ns][0] = g_W1p[(kr) * 256 + n0 + ns * 8 + gr];
            bw[0][ns][1] = g_W1p[(kr + 4) * 256 + n0 + ns * 8 + gr];
            bw[1][ns][0] = g_W1p[(8 + kr) * 256 + n0 + ns * 8 + gr];
            bw[1][ns][1] = g_W1p[(12 + kr) * 256 + n0 + ns * 8 + gr];
        }
        for (int ks = 0; ks < 16; ks++) {
            int kp0 = ks * 8;
            int sl = ks & 1;
            uint32_t cur[4][2];
#pragma unroll
            for (int ns = 0; ns < 4; ns++) {
                cur[ns][0] = bw[sl][ns][0];
                cur[ns][1] = bw[sl][ns][1];
            }
            if (ks < 14) {
#pragma unroll
                for (int ns = 0; ns < 4; ns++) {
                    bw[sl][ns][0] = g_W1p[(kp0 + 16 + kr) * 256 + n0 + ns * 8 + gr];
                    bw[sl][ns][1] = g_W1p[(kp0 + 20 + kr) * 256 + n0 + ns * 8 + gr];
                }
            }
#pragma unroll
            for (int mt = 0; mt < 3; mt++) {
                int row = mt * 16 + gr;
                uint32_t a0 = dirfS[row * PW + kp0 + kr];
                uint32_t a1 = dirfS[(row + 8) * PW + kp0 + kr];
                uint32_t a2 = dirfS[row * PW + kp0 + kr + 4];
                uint32_t a3 = dirfS[(row + 8) * PW + kp0 + kr + 4];
#pragma unroll
                for (int ns = 0; ns < 4; ns++)
                    mma16(acc[mt][ns], a0, a1, a2, a3, cur[ns][0], cur[ns][1]);
            }
        }
#pragma unroll
        for (int ns = 0; ns < 4; ns++) {
            int col0 = n0 + ns * 8 + 2 * kr;
            float bv0 = bd1[col0], bv1 = bd1[col0 + 1];
            int wp = (col0 >> 1);
#pragma unroll
            for (int mt = 0; mt < 3; mt++) {
                int row = mt * 16 + gr;
                t1S[row * PW + wp] = packbf(silu_f(acc[mt][ns][0] + bv0), silu_f(acc[mt][ns][1] + bv1));
                t1S[(row + 8) * PW + wp] = packbf(silu_f(acc[mt][ns][2] + bv0), silu_f(acc[mt][ns][3] + bv1));
            }
        }
    }
    __syncthreads();

    // phase 4: dp = silu(t1(48x256) @ Wd2 + bd2); mask(bf16) *= dp; warp owns 16 cols
    {
        int n0 = w * 16;
        float acc[3][2][4];
#pragma unroll
        for (int mt = 0; mt < 3; mt++)
#pragma unroll
            for (int ns = 0; ns < 2; ns++)
#pragma unroll
                for (int c = 0; c < 4; c++) acc[mt][ns][c] = 0.f;
        uint32_t bw[2][2][2];
#pragma unroll
        for (int ns = 0; ns < 2; ns++) {
            bw[0][ns][0] = g_W2p[(kr) * 128 + n0 + ns * 8 + gr];
            bw[0][ns][1] = g_W2p[(kr + 4) * 128 + n0 + ns * 8 + gr];
            bw[1][ns][0] = g_W2p[(8 + kr) * 128 + n0 + ns * 8 + gr];
            bw[1][ns][1] = g_W2p[(12 + kr) * 128 + n0 + ns * 8 + gr];
        }
        for (int ks = 0; ks < 16; ks++) {
            int kp0 = ks * 8;
            int sl = ks & 1;
            uint32_t cur[2][2];
#pragma unroll
            for (int ns = 0; ns < 2; ns++) {
                cur[ns][0] = bw[sl][ns][0];
                cur[ns][1] = bw[sl][ns][1];
            }
            if (ks < 14) {
#pragma unroll
                for (int ns = 0; ns < 2; ns++) {
                    bw[sl][ns][0] = g_W2p[(kp0 + 16 + kr) * 128 + n0 + ns * 8 + gr];
                    bw[sl][ns][1] = g_W2p[(kp0 + 20 + kr) * 128 + n0 + ns * 8 + gr];
                }
            }
#pragma unroll
            for (int mt = 0; mt < 3; mt++) {
                int row = mt * 16 + gr;
                uint32_t a0 = t1S[row * PW + kp0 + kr];
                uint32_t a1 = t1S[(row + 8) * PW + kp0 + kr];
                uint32_t a2 = t1S[row * PW + kp0 + kr + 4];
                uint32_t a3 = t1S[(row + 8) * PW + kp0 + kr + 4];
#pragma unroll
                for (int ns = 0; ns < 2; ns++)
                    mma16(acc[mt][ns], a0, a1, a2, a3, cur[ns][0], cur[ns][1]);
            }
        }
#pragma unroll
        for (int ns = 0; ns < 2; ns++) {
            int col0 = n0 + ns * 8 + 2 * kr;
            float bv0 = bd2[col0], bv1 = bd2[col0 + 1];
#pragma unroll
            for (int mt = 0; mt < 3; mt++) {
                int row = mt * 16 + gr;
                size_t idx0 = ((size_t)bi * N + j0 + row) * (HID / 2) + (col0 >> 1);
                float2 m0 = unpackbf(g_maskh[idx0]);
                g_maskh[idx0] = packbf(m0.x * silu_f(acc[mt][ns][0] + bv0),
                                       m0.y * silu_f(acc[mt][ns][1] + bv1));
                size_t idx1 = ((size_t)bi * N + j0 + row + 8) * (HID / 2) + (col0 >> 1);
                float2 m1 = unpackbf(g_maskh[idx1]);
                g_maskh[idx1] = packbf(m1.x * silu_f(acc[mt][ns][2] + bv0),
                                       m1.y * silu_f(acc[mt][ns][3] + bv1));
            }
        }
    }
}

// ---------------- K7: readout ----------------
__global__ void k_read(const int* __restrict__ z, const float* __restrict__ Wout,
                       const float* __restrict__ bout, float* __restrict__ out) {
    int b = blockIdx.x;
    int h = threadIdx.x;
    __shared__ float red[4];
    float acc = 0.0f;
    for (int i = 0; i < N; i++) {
        if (z[b * N + i] != 0) acc += g_s[(b * N + i) * HID + h];
    }
    float p = acc * Wout[h];
    float s = blksum128(p, red);
    if (h == 0) out[b] = s + bout[0];
}

// ---------------- launch ----------------
extern "C" void kernel_launch(void* const* d_in, const int* in_sizes, int n_in,
                              void* d_out, int out_size) {
    const int* z = (const int*)d_in[0];
    const float* pos = (const float*)d_in[1];
    const float* emb = (const float*)d_in[2];
    const float* Wef = (const float*)d_in[3];
    const float* bef = (const float*)d_in[4];
    const float* Ws2v = (const float*)d_in[5];
    const float* bs2v = (const float*)d_in[6];
    const float* Wq = (const float*)d_in[7];
    const float* Wk = (const float*)d_in[8];
    const float* Wd1 = (const float*)d_in[9];
    const float* bd1 = (const float*)d_in[10];
    const float* Wd2 = (const float*)d_in[11];
    const float* bd2 = (const float*)d_in[12];
    const float* Wint = (const float*)d_in[13];
    const float* bint = (const float*)d_in[14];
    const float* Wout = (const float*)d_in[15];
    const float* bout = (const float*)d_in[16];
    float* out = (float*)d_out;

    cudaFuncSetAttribute(k_dir, cudaFuncAttributeMaxDynamicSharedMemorySize, SMEM_DIR_BYTES);
    cudaFuncSetAttribute(k_geomne, cudaFuncAttributeMaxDynamicSharedMemorySize, GEOM_SMEM);

    dim3 g(N, B);
    dim3 gd(N, B, 2);
    k_init<<<INIT_BLKS, 128>>>(z, emb, Wd1, Wd2);
    k_geomne<<<g, 256, GEOM_SMEM>>>(z, pos, Wef, bef);
    k_lin4<<<BN / LIN_R, 256>>>(Ws2v, bs2v);  // -> g_s1
    k_v<<<g, 256>>>();
    k_qk4<<<BN / QK_R, 128>>>(Wq, Wk);
    k_dir<<<gd, 256, SMEM_DIR_BYTES>>>(bd1, bd2);
    // message-passing: lin(0) then fused agg(l)+lin(l+1)
    k_lin4<<<BN / LIN_R, 256>>>(Wint, bint);  // -> g_s1 (layer 0 sl)
    k_agglin<<<BN / LIN_R, 256>>>(Wint + 1 * HID * HID, bint + 1 * HID, 0, 1);  // agg0 + lin1 -> g_s1b
    k_agglin<<<BN / LIN_R, 256>>>(Wint + 2 * HID * HID, bint + 2 * HID, 1, 1);  // agg1 + lin2 -> g_s1
    k_agglin<<<BN / LIN_R, 256>>>(Wint + 3 * HID * HID, bint + 3 * HID, 0, 1);  // agg2 + lin3 -> g_s1b
    k_agglin<<<BN / LIN_R, 256>>>(Wint, bint, 1, 0);                            // agg3 only
    k_read<<<B, 128>>>(z, Wout, bout, out);
}